// round 9
// baseline (speedup 1.0000x reference)
#include <cuda_runtime.h>
#include <cuda_fp16.h>
#include <math.h>
#include <stdint.h>

#define BB   2
#define NN   2048
#define HID  896
#define HQ   14
#define HKV  2
#define DD   64
#define MTOT (BB*NN)          // 4096 tokens
#define NQKV 1152             // 896 Q + 128 K + 128 V

// ---- scratch (device globals: no allocations allowed) ----
__device__ float  g_qkv[MTOT*NQKV];    // fused QKV proj output (fp32)
__device__ __half g_kvh[MTOT*256];     // roped K (0..127) + V (128..255), fp16
__device__ __half g_oh[MTOT*HID];      // attention out, fp16
__device__ __half g_hsh[MTOT*HID];     // fp16 hidden_states
__device__ __half g_wqkvh[HID*NQKV];   // packed [896(k)][1152(n)] fp16 (natural)
__device__ float  g_bqkv[NQKV];        // packed bias fp32
__device__ __half g_owh[HID*HID];      // o_w [896(k)][896(n)] fp16 (natural)

// ============================================================
// helpers
// ============================================================
__device__ __forceinline__ float ex2f(float x) {
    float y;
    asm("ex2.approx.ftz.f32 %0, %1;" : "=f"(y) : "f"(x));
    return y;
}
__device__ __forceinline__ uint32_t ex2_h2(uint32_t x) {
    uint32_t y;
    asm("ex2.approx.f16x2 %0, %1;" : "=r"(y) : "r"(x));
    return y;
}
__device__ __forceinline__ void mma_f16(float c[4],
    uint32_t a0, uint32_t a1, uint32_t a2, uint32_t a3,
    uint32_t b0, uint32_t b1)
{
    asm volatile(
        "mma.sync.aligned.m16n8k16.row.col.f32.f16.f16.f32 "
        "{%0,%1,%2,%3}, {%4,%5,%6,%7}, {%8,%9}, {%0,%1,%2,%3};\n"
        : "+f"(c[0]), "+f"(c[1]), "+f"(c[2]), "+f"(c[3])
        : "r"(a0), "r"(a1), "r"(a2), "r"(a3), "r"(b0), "r"(b1));
}
__device__ __forceinline__ void ldsm_x4(uint32_t& r0, uint32_t& r1,
                                        uint32_t& r2, uint32_t& r3, uint32_t sa)
{
    asm volatile("ldmatrix.sync.aligned.m8n8.x4.shared.b16 {%0,%1,%2,%3}, [%4];"
                 : "=r"(r0), "=r"(r1), "=r"(r2), "=r"(r3) : "r"(sa));
}
__device__ __forceinline__ void ldsm_x4_trans(uint32_t& r0, uint32_t& r1,
                                              uint32_t& r2, uint32_t& r3, uint32_t sa)
{
    asm volatile("ldmatrix.sync.aligned.m8n8.x4.trans.shared.b16 {%0,%1,%2,%3}, [%4];"
                 : "=r"(r0), "=r"(r1), "=r"(r2), "=r"(r3) : "r"(sa));
}
__device__ __forceinline__ void ldsm_x2(uint32_t& r0, uint32_t& r1, uint32_t sa)
{
    asm volatile("ldmatrix.sync.aligned.m8n8.x2.shared.b16 {%0,%1}, [%2];"
                 : "=r"(r0), "=r"(r1) : "r"(sa));
}
__device__ __forceinline__ void ldsm_x2_trans(uint32_t& r0, uint32_t& r1, uint32_t sa)
{
    asm volatile("ldmatrix.sync.aligned.m8n8.x2.trans.shared.b16 {%0,%1}, [%2];"
                 : "=r"(r0), "=r"(r1) : "r"(sa));
}
__device__ __forceinline__ void cp_async16(void* sdst, const void* gsrc) {
    unsigned sa = (unsigned)__cvta_generic_to_shared(sdst);
    asm volatile("cp.async.cg.shared.global [%0], [%1], 16;\n"
                 :: "r"(sa), "l"(gsrc));
}
__device__ __forceinline__ void cp_commit() {
    asm volatile("cp.async.commit_group;\n");
}
__device__ __forceinline__ void cp_wait0() {
    asm volatile("cp.async.wait_group 0;\n");
}
__device__ __forceinline__ uint32_t h2pack(float x, float y) {
    __half2 h = __floats2half2_rn(x, y);
    return *(uint32_t*)&h;
}

// ============================================================
// prep kernels (all fully coalesced)
// ============================================================
__global__ void f2h4_kernel(const float4* __restrict__ src,
                            __half* __restrict__ dst, int n4)
{
    int idx = blockIdx.x * blockDim.x + threadIdx.x;
    if (idx >= n4) return;
    float4 v = src[idx];
    __half2 h0 = __floats2half2_rn(v.x, v.y);
    __half2 h1 = __floats2half2_rn(v.z, v.w);
    *(uint2*)(dst + idx * 4) = make_uint2(*(uint32_t*)&h0, *(uint32_t*)&h1);
}

__global__ void pack_qkv_kernel(
    const float* __restrict__ qw, const float* __restrict__ kw,
    const float* __restrict__ vw, const float* __restrict__ qb,
    const float* __restrict__ kb, const float* __restrict__ vb,
    __half* __restrict__ w, float* __restrict__ bias)
{
    int idx = blockIdx.x * blockDim.x + threadIdx.x;
    const int total = HID * NQKV;
    if (idx < total) {
        int k = idx / NQKV, n = idx % NQKV;
        float v = (n < 896) ? qw[(size_t)k * 896 + n]
                : (n < 1024) ? kw[(size_t)k * 128 + (n - 896)]
                             : vw[(size_t)k * 128 + (n - 1024)];
        w[idx] = __float2half(v);
    }
    if (idx < NQKV) {
        bias[idx] = (idx < 896) ? qb[idx]
                  : (idx < 1024) ? kb[idx - 896] : vb[idx - 1024];
    }
}

// ============================================================
// fp16 mma GEMM (unchanged from R8)
// ============================================================
__global__ __launch_bounds__(256, 2) void gemm_h(
    const __half* __restrict__ A, const __half* __restrict__ B,
    const float* __restrict__ bias, float* __restrict__ C,
    int Nw, int Nc, int K)
{
    extern __shared__ __align__(128) char dynsm[];
    __half* As = (__half*)dynsm;                  // [2][128*72]
    __half* Bs = As + 2 * 128 * 72;               // [2][64*136]
    const uint32_t As_u = (uint32_t)__cvta_generic_to_shared(As);
    const uint32_t Bs_u = (uint32_t)__cvta_generic_to_shared(Bs);
    const int STGA = 128 * 72;
    const int STGB = 64 * 136;

    const int tid = threadIdx.x;
    const int lane = tid & 31;
    const int warp = tid >> 5;
    const int warpM = warp >> 2, warpN = warp & 3;
    const int bx = blockIdx.x, by = blockIdx.y;
    const int qrow = lane >> 2, qk = lane & 3;

    const __half* Ag = A + (size_t)(by * 128) * K;
    const __half* Bg = B + bx * 128;
    const int a_row = tid >> 3, a_ch = tid & 7;
    const int b_row = tid >> 4, b_ch = tid & 15;

    float acc[4][4][4];
#pragma unroll
    for (int mf = 0; mf < 4; mf++)
#pragma unroll
        for (int nf = 0; nf < 4; nf++)
#pragma unroll
            for (int i = 0; i < 4; i++) acc[mf][nf][i] = 0.f;

    const int a_row_l = warpM * 64 + (lane & 7) + ((lane >> 3) & 1) * 8;
    const int a_ksel  = (lane >> 4) & 1;
    const int b_col_l = warpN * 32;
    const int b_lane_r = lane & 15;

#pragma unroll
    for (int t = 0; t < 4; t++) {
        int ra = a_row + t * 32;
        cp_async16(As + ra * 72 + a_ch * 8, Ag + (size_t)ra * K + a_ch * 8);
        int rb = b_row + t * 16;
        cp_async16(Bs + rb * 136 + b_ch * 8, Bg + (size_t)rb * Nw + b_ch * 8);
    }
    cp_commit();

    const int NKT = K / 64;
    for (int kt = 0; kt < NKT; kt++) {
        cp_wait0();
        __syncthreads();
        const int cur = kt & 1;
        if (kt + 1 < NKT) {
            const int ko = (kt + 1) * 64;
            __half* Ad = As + (cur ^ 1) * STGA;
            __half* Bd = Bs + (cur ^ 1) * STGB;
#pragma unroll
            for (int t = 0; t < 4; t++) {
                int ra = a_row + t * 32;
                cp_async16(Ad + ra * 72 + a_ch * 8, Ag + (size_t)ra * K + ko + a_ch * 8);
                int rb = b_row + t * 16;
                cp_async16(Bd + rb * 136 + b_ch * 8, Bg + (size_t)(ko + rb) * Nw + b_ch * 8);
            }
        }
        cp_commit();

        const uint32_t Ab = As_u + cur * STGA * 2;
        const uint32_t Bb = Bs_u + cur * STGB * 2;
#pragma unroll
        for (int ch = 0; ch < 4; ch++) {
            uint32_t af[4][4];
#pragma unroll
            for (int mf = 0; mf < 4; mf++) {
                uint32_t sa = Ab + (a_row_l + mf * 16) * 144 + ch * 32 + a_ksel * 16;
                ldsm_x4(af[mf][0], af[mf][1], af[mf][2], af[mf][3], sa);
            }
#pragma unroll
            for (int nf = 0; nf < 4; nf++) {
                uint32_t b0, b1;
                uint32_t sb = Bb + (ch * 16 + b_lane_r) * 272 + (b_col_l + nf * 8) * 2;
                ldsm_x2_trans(b0, b1, sb);
#pragma unroll
                for (int mf = 0; mf < 4; mf++)
                    mma_f16(acc[mf][nf], af[mf][0], af[mf][1], af[mf][2], af[mf][3], b0, b1);
            }
        }
    }

#pragma unroll
    for (int nf = 0; nf < 4; nf++) {
        int col = bx * 128 + warpN * 32 + nf * 8 + qk * 2;
        float b0 = bias ? bias[col] : 0.f;
        float b1 = bias ? bias[col + 1] : 0.f;
#pragma unroll
        for (int mf = 0; mf < 4; mf++) {
            int row = by * 128 + warpM * 64 + mf * 16 + qrow;
            float2 o0 = { acc[mf][nf][0] + b0, acc[mf][nf][1] + b1 };
            float2 o1 = { acc[mf][nf][2] + b0, acc[mf][nf][3] + b1 };
            *(float2*)(C + (size_t)row * Nc + col) = o0;
            *(float2*)(C + (size_t)(row + 8) * Nc + col) = o1;
        }
    }
}

// ============================================================
// RoPE (unchanged from R8)
// ============================================================
__global__ void rope_qkv(float* __restrict__ qkv, __half* __restrict__ kvh,
                         const int* __restrict__ pos)
{
    int idx = blockIdx.x * blockDim.x + threadIdx.x;
    const int tot = MTOT * 18 * 32;
    if (idx >= tot) return;
    int i = idx & 31;
    int slot = (idx >> 5) % 18;
    int t = idx / (32 * 18);

    if (slot >= 16) {
        int h = slot - 16;
        size_t src = (size_t)t * NQKV + 1024 + h * DD + i;
        size_t dst = (size_t)t * 256 + 128 + h * DD + i;
        kvh[dst]      = __float2half(qkv[src]);
        kvh[dst + 32] = __float2half(qkv[src + 32]);
        return;
    }
    float p = (float)pos[t];
    const float cexp = -0.622861517791378f;
    float inv = exp2f((float)i * cexp);
    float ang = p * inv;
    float sn, cs;
    sincosf(ang, &sn, &cs);
    if (slot < HQ) {
        size_t base = (size_t)t * NQKV + slot * DD + i;
        float x1 = qkv[base], x2 = qkv[base + 32];
        qkv[base]      = x1 * cs - x2 * sn;
        qkv[base + 32] = x2 * cs + x1 * sn;
    } else {
        int h = slot - HQ;
        size_t src = (size_t)t * NQKV + 896 + h * DD + i;
        float x1 = qkv[src], x2 = qkv[src + 32];
        size_t dst = (size_t)t * 256 + h * DD + i;
        kvh[dst]      = __float2half(x1 * cs - x2 * sn);
        kvh[dst + 32] = __float2half(x2 * cs + x1 * sn);
    }
}

// ============================================================
// Causal GQA flash attention, fp16 mma.sync.
// R9: ldsm.x4 K-frags, ex2.f16x2 softmax, ones-MMA row sums,
//     ldsm.x4.trans V-frags.
// ============================================================
__global__ __launch_bounds__(128, 4) void attn_mma(
    const float* __restrict__ QKV, const __half* __restrict__ KVH,
    __half* __restrict__ O)
{
    extern __shared__ __align__(128) char dynsm2[];
    __half* ks = (__half*)dynsm2;             // [2][64*72]
    __half* vs = ks + 2 * 64 * 72;            // [2][64*72]
    const uint32_t ks_u = (uint32_t)__cvta_generic_to_shared(ks);
    const uint32_t vs_u = (uint32_t)__cvta_generic_to_shared(vs);
    const int STG = 64 * 72;
    const uint32_t ONES = 0x3C003C00u;        // half2(1,1)

    const int bh = blockIdx.x;
    const int b = bh / HQ, h = bh % HQ;
    const int q0 = ((int)gridDim.y - 1 - (int)blockIdx.y) * 64;  // heavy first
    const int kh = h / (HQ / HKV);
    const int tid = threadIdx.x, warp = tid >> 5, lane = tid & 31;
    const int qrow = lane >> 2, qk = lane & 3;
    const float QSCALE = 0.125f * 1.44269504f;  // scale * log2(e)

    const __half* Kb = KVH + (size_t)(b * NN) * 256 + kh * DD;
    const __half* Vb = KVH + (size_t)(b * NN) * 256 + 128 + kh * DD;

    const int ld_row = tid >> 3, ld_ch = tid & 7;

#pragma unroll
    for (int t = 0; t < 4; t++) {
        int r = ld_row + t * 16;
        cp_async16(ks + r * 72 + ld_ch * 8, Kb + (size_t)r * 256 + ld_ch * 8);
        cp_async16(vs + r * 72 + ld_ch * 8, Vb + (size_t)r * 256 + ld_ch * 8);
    }
    cp_commit();

    uint32_t qa[4][4];
    {
        const int r0 = q0 + warp * 16 + qrow;
        const float* qp0 = QKV + (size_t)(b * NN + r0) * NQKV + h * DD;
        const float* qp1 = qp0 + (size_t)8 * NQKV;
#pragma unroll
        for (int ch = 0; ch < 4; ch++) {
            float2 v0 = *(const float2*)(qp0 + ch * 16 + 2 * qk);
            float2 v1 = *(const float2*)(qp1 + ch * 16 + 2 * qk);
            float2 v2 = *(const float2*)(qp0 + ch * 16 + 8 + 2 * qk);
            float2 v3 = *(const float2*)(qp1 + ch * 16 + 8 + 2 * qk);
            qa[ch][0] = h2pack(v0.x * QSCALE, v0.y * QSCALE);
            qa[ch][1] = h2pack(v1.x * QSCALE, v1.y * QSCALE);
            qa[ch][2] = h2pack(v2.x * QSCALE, v2.y * QSCALE);
            qa[ch][3] = h2pack(v3.x * QSCALE, v3.y * QSCALE);
        }
    }

    float o[8][4];
#pragma unroll
    for (int nf = 0; nf < 8; nf++)
#pragma unroll
        for (int i = 0; i < 4; i++) o[nf][i] = 0.f;
    float m0 = -1e30f, m1 = -1e30f, l0 = 0.f, l1 = 0.f;

    const int r0g = q0 + warp * 16 + qrow;
    const int r1g = r0g + 8;
    const int ktiles = q0 / 64 + 1;
    const int kt_diag = ktiles - 1;

    // ldsm addressing
    const int k_row_l = lane & 7;              // + nf*8
    const int k_ksel  = (lane >> 3) & 1;       // k lower/upper 8 within chunk
    const int k_chsel = (lane >> 4) & 1;       // ch pair member
    const int v_row_l = lane & 15;             // + jk*16
    const int v_csel  = (lane >> 4) & 1;       // jn pair member

    for (int kt = 0; kt < ktiles; kt++) {
        cp_wait0();
        __syncthreads();
        const int cur = kt & 1;
        if (kt + 1 < ktiles) {
            const int base = (kt + 1) * 64;
            __half* kd = ks + (cur ^ 1) * STG;
            __half* vd = vs + (cur ^ 1) * STG;
#pragma unroll
            for (int t = 0; t < 4; t++) {
                int r = ld_row + t * 16;
                cp_async16(kd + r * 72 + ld_ch * 8, Kb + (size_t)(base + r) * 256 + ld_ch * 8);
                cp_async16(vd + r * 72 + ld_ch * 8, Vb + (size_t)(base + r) * 256 + ld_ch * 8);
            }
        }
        cp_commit();

        const uint32_t kc_u = ks_u + cur * STG * 2;

        // ---- S = Q @ K^T (log2-scaled); K frags via ldsm.x4 ----
        float sc[8][4];
#pragma unroll
        for (int nf = 0; nf < 8; nf++)
#pragma unroll
            for (int i = 0; i < 4; i++) sc[nf][i] = 0.f;
#pragma unroll
        for (int chp = 0; chp < 2; chp++) {
#pragma unroll
            for (int nf = 0; nf < 8; nf++) {
                uint32_t r0, r1, r2, r3;
                uint32_t sa = kc_u + (nf * 8 + k_row_l) * 144
                            + (chp * 2 + k_chsel) * 32 + k_ksel * 16;
                ldsm_x4(r0, r1, r2, r3, sa);
                mma_f16(sc[nf], qa[chp*2][0], qa[chp*2][1], qa[chp*2][2], qa[chp*2][3], r0, r1);
                mma_f16(sc[nf], qa[chp*2+1][0], qa[chp*2+1][1], qa[chp*2+1][2], qa[chp*2+1][3], r2, r3);
            }
        }

        // ---- causal mask ----
        if (kt == kt_diag) {
#pragma unroll
            for (int nf = 0; nf < 8; nf++) {
                int c = kt * 64 + nf * 8 + qk * 2;
                if (c > r0g)     sc[nf][0] = -1e30f;
                if (c + 1 > r0g) sc[nf][1] = -1e30f;
                if (c > r1g)     sc[nf][2] = -1e30f;
                if (c + 1 > r1g) sc[nf][3] = -1e30f;
            }
        }

        // ---- online softmax (log2 domain, f16x2 ex2) ----
        float mx0 = -1e30f, mx1 = -1e30f;
#pragma unroll
        for (int nf = 0; nf < 8; nf++) {
            mx0 = fmaxf(mx0, fmaxf(sc[nf][0], sc[nf][1]));
            mx1 = fmaxf(mx1, fmaxf(sc[nf][2], sc[nf][3]));
        }
        mx0 = fmaxf(mx0, __shfl_xor_sync(0xffffffffu, mx0, 1));
        mx0 = fmaxf(mx0, __shfl_xor_sync(0xffffffffu, mx0, 2));
        mx1 = fmaxf(mx1, __shfl_xor_sync(0xffffffffu, mx1, 1));
        mx1 = fmaxf(mx1, __shfl_xor_sync(0xffffffffu, mx1, 2));
        float mn0 = fmaxf(m0, mx0), mn1 = fmaxf(m1, mx1);
        float al0 = ex2f(m0 - mn0), al1 = ex2f(m1 - mn1);

        // P fragments: pack (s - m) pairs, exp2 in fp16x2
        uint32_t pa[8][2];
#pragma unroll
        for (int nf = 0; nf < 8; nf++) {
            pa[nf][0] = ex2_h2(h2pack(sc[nf][0] - mn0, sc[nf][1] - mn0));
            pa[nf][1] = ex2_h2(h2pack(sc[nf][2] - mn1, sc[nf][3] - mn1));
        }

        // row sums via ones-MMA (fp32 acc, same P as PV)
        float lt[4] = {0.f, 0.f, 0.f, 0.f};
#pragma unroll
        for (int jk = 0; jk < 4; jk++)
            mma_f16(lt, pa[2*jk][0], pa[2*jk][1], pa[2*jk+1][0], pa[2*jk+1][1],
                    ONES, ONES);
        l0 = l0 * al0 + lt[0];  m0 = mn0;
        l1 = l1 * al1 + lt[2];  m1 = mn1;
#pragma unroll
        for (int nf = 0; nf < 8; nf++) {
            o[nf][0] *= al0; o[nf][1] *= al0;
            o[nf][2] *= al1; o[nf][3] *= al1;
        }

        // ---- O += P @ V : V frags via ldsm.x4.trans ----
        const uint32_t vc_u = vs_u + cur * STG * 2;
#pragma unroll
        for (int jk = 0; jk < 4; jk++) {
            uint32_t a0 = pa[2*jk][0],   a1 = pa[2*jk][1];
            uint32_t a2 = pa[2*jk+1][0], a3 = pa[2*jk+1][1];
#pragma unroll
            for (int jnp = 0; jnp < 4; jnp++) {
                uint32_t b0, b1, b2, b3;
                uint32_t sb = vc_u + (jk * 16 + v_row_l) * 144
                            + (jnp * 16 + v_csel * 8) * 2;
                ldsm_x4_trans(b0, b1, b2, b3, sb);
                mma_f16(o[2*jnp],   a0, a1, a2, a3, b0, b1);
                mma_f16(o[2*jnp+1], a0, a1, a2, a3, b2, b3);
            }
        }
    }

    float inv0 = 1.0f / (l0 + 1e-8f);
    float inv1 = 1.0f / (l1 + 1e-8f);
    __half* op0 = O + (size_t)(b * NN + r0g) * HID + h * DD;
    __half* op1 = O + (size_t)(b * NN + r1g) * HID + h * DD;
#pragma unroll
    for (int nf = 0; nf < 8; nf++) {
        int d = nf * 8 + qk * 2;
        *(uint32_t*)(op0 + d) = h2pack(o[nf][0] * inv0, o[nf][1] * inv0);
        *(uint32_t*)(op1 + d) = h2pack(o[nf][2] * inv1, o[nf][3] * inv1);
    }
}

// ============================================================
extern "C" void kernel_launch(void* const* d_in, const int* in_sizes, int n_in,
                              void* d_out, int out_size)
{
    const float* hs  = (const float*)d_in[0];
    const int*   pos = (const int*)d_in[1];
    const float* q_w = (const float*)d_in[2];
    const float* q_b = (const float*)d_in[3];
    const float* k_w = (const float*)d_in[4];
    const float* k_b = (const float*)d_in[5];
    const float* v_w = (const float*)d_in[6];
    const float* v_b = (const float*)d_in[7];
    const float* o_w = (const float*)d_in[8];
    float* out = (float*)d_out;

    float *pqkv, *pbqkv;
    __half *pkvh, *poh, *phsh, *pwqkvh, *powh;
    cudaGetSymbolAddress((void**)&pqkv,   g_qkv);
    cudaGetSymbolAddress((void**)&pkvh,   g_kvh);
    cudaGetSymbolAddress((void**)&poh,    g_oh);
    cudaGetSymbolAddress((void**)&phsh,   g_hsh);
    cudaGetSymbolAddress((void**)&pwqkvh, g_wqkvh);
    cudaGetSymbolAddress((void**)&pbqkv,  g_bqkv);
    cudaGetSymbolAddress((void**)&powh,   g_owh);

    const int GEMM_SMEM = 2 * (128*72 + 64*136) * 2;   // 71680 B
    const int ATTN_SMEM = 2 * (64*72 + 64*72) * 2;     // 36864 B
    cudaFuncSetAttribute(gemm_h,   cudaFuncAttributeMaxDynamicSharedMemorySize, GEMM_SMEM);
    cudaFuncSetAttribute(attn_mma, cudaFuncAttributeMaxDynamicSharedMemorySize, ATTN_SMEM);

    // prep (all coalesced)
    {
        int n4 = MTOT * HID / 4;
        f2h4_kernel<<<(n4 + 255) / 256, 256>>>((const float4*)hs, phsh, n4);
        int m4 = HID * HID / 4;
        f2h4_kernel<<<(m4 + 255) / 256, 256>>>((const float4*)o_w, powh, m4);
        int tp = HID * NQKV;
        pack_qkv_kernel<<<(tp + 255) / 256, 256>>>(q_w, k_w, v_w, q_b, k_b, v_b,
                                                   pwqkvh, pbqkv);
    }
    // fused QKV projection
    gemm_h<<<dim3(9, 32), 256, GEMM_SMEM>>>(phsh, pwqkvh, pbqkv, pqkv, NQKV, NQKV, HID);
    // RoPE
    {
        int tot = MTOT * 18 * 32;
        rope_qkv<<<(tot + 255) / 256, 256>>>(pqkv, pkvh, pos);
    }
    // causal GQA attention -> fp16 O
    attn_mma<<<dim3(BB * HQ, NN / 64), 128, ATTN_SMEM>>>(pqkv, pkvh, poh);
    // output projection
    gemm_h<<<dim3(7, 32), 256, GEMM_SMEM>>>(poh, powh, nullptr, out, HID, HID, HID);
}

// round 10
// speedup vs baseline: 1.5557x; 1.5557x over previous
#include <cuda_runtime.h>
#include <cuda_fp16.h>
#include <math.h>
#include <stdint.h>

#define BB   2
#define NN   2048
#define HID  896
#define HQ   14
#define HKV  2
#define DD   64
#define MTOT (BB*NN)          // 4096 tokens
#define NQKV 1152             // 896 Q + 128 K + 128 V

// ---- scratch (device globals: no allocations allowed) ----
__device__ float  g_qkv[MTOT*NQKV];    // fused QKV proj output (fp32)
__device__ __half g_kvh[MTOT*256];     // roped K (0..127) + V (128..255), fp16
__device__ __half g_oh[MTOT*HID];      // attention out, fp16
__device__ __half g_hsh[MTOT*HID];     // fp16 hidden_states
__device__ __half g_wqkvh[HID*NQKV];   // packed [896(k)][1152(n)] fp16 (natural)
__device__ float  g_bqkv[NQKV];        // packed bias fp32
__device__ __half g_owh[HID*HID];      // o_w [896(k)][896(n)] fp16 (natural)

// ============================================================
// helpers
// ============================================================
__device__ __forceinline__ float ex2f(float x) {
    float y;
    asm("ex2.approx.ftz.f32 %0, %1;" : "=f"(y) : "f"(x));
    return y;
}
__device__ __forceinline__ uint32_t ex2_h2(uint32_t x) {
    uint32_t y;
    asm("ex2.approx.f16x2 %0, %1;" : "=r"(y) : "r"(x));
    return y;
}
__device__ __forceinline__ void mma_f16(float c[4],
    uint32_t a0, uint32_t a1, uint32_t a2, uint32_t a3,
    uint32_t b0, uint32_t b1)
{
    asm volatile(
        "mma.sync.aligned.m16n8k16.row.col.f32.f16.f16.f32 "
        "{%0,%1,%2,%3}, {%4,%5,%6,%7}, {%8,%9}, {%0,%1,%2,%3};\n"
        : "+f"(c[0]), "+f"(c[1]), "+f"(c[2]), "+f"(c[3])
        : "r"(a0), "r"(a1), "r"(a2), "r"(a3), "r"(b0), "r"(b1));
}
__device__ __forceinline__ void ldsm_x4(uint32_t& r0, uint32_t& r1,
                                        uint32_t& r2, uint32_t& r3, uint32_t sa)
{
    asm volatile("ldmatrix.sync.aligned.m8n8.x4.shared.b16 {%0,%1,%2,%3}, [%4];"
                 : "=r"(r0), "=r"(r1), "=r"(r2), "=r"(r3) : "r"(sa));
}
__device__ __forceinline__ void ldsm_x4_trans(uint32_t& r0, uint32_t& r1,
                                              uint32_t& r2, uint32_t& r3, uint32_t sa)
{
    asm volatile("ldmatrix.sync.aligned.m8n8.x4.trans.shared.b16 {%0,%1,%2,%3}, [%4];"
                 : "=r"(r0), "=r"(r1), "=r"(r2), "=r"(r3) : "r"(sa));
}
__device__ __forceinline__ void ldsm_x2_trans(uint32_t& r0, uint32_t& r1, uint32_t sa)
{
    asm volatile("ldmatrix.sync.aligned.m8n8.x2.trans.shared.b16 {%0,%1}, [%2];"
                 : "=r"(r0), "=r"(r1) : "r"(sa));
}
__device__ __forceinline__ void cp_async16(void* sdst, const void* gsrc) {
    unsigned sa = (unsigned)__cvta_generic_to_shared(sdst);
    asm volatile("cp.async.cg.shared.global [%0], [%1], 16;\n"
                 :: "r"(sa), "l"(gsrc));
}
__device__ __forceinline__ void cp_commit() {
    asm volatile("cp.async.commit_group;\n");
}
__device__ __forceinline__ void cp_wait0() {
    asm volatile("cp.async.wait_group 0;\n");
}
__device__ __forceinline__ uint32_t h2pack(float x, float y) {
    __half2 h = __floats2half2_rn(x, y);
    return *(uint32_t*)&h;
}

// ============================================================
// fused prep: hs->fp16, o_w->fp16, qkv pack (all coalesced, one launch)
// ============================================================
#define PREP_NA (MTOT*HID/4)      // 917504
#define PREP_NB (HID*HID/4)       // 200704
#define PREP_NC (HID*NQKV/4)      // 258048
#define PREP_TOT (PREP_NA + PREP_NB + PREP_NC)

__global__ void prep_all(
    const float4* __restrict__ hs, const float4* __restrict__ ow,
    const float* __restrict__ qw, const float* __restrict__ kw,
    const float* __restrict__ vw, const float* __restrict__ qb,
    const float* __restrict__ kb, const float* __restrict__ vb,
    __half* __restrict__ hsh, __half* __restrict__ owh,
    __half* __restrict__ wqkv, float* __restrict__ bias)
{
    int idx = blockIdx.x * blockDim.x + threadIdx.x;
    if (idx < PREP_NA) {
        float4 v = hs[idx];
        __half2 h0 = __floats2half2_rn(v.x, v.y);
        __half2 h1 = __floats2half2_rn(v.z, v.w);
        *(uint2*)(hsh + idx * 4) = make_uint2(*(uint32_t*)&h0, *(uint32_t*)&h1);
    } else if (idx < PREP_NA + PREP_NB) {
        int j = idx - PREP_NA;
        float4 v = ow[j];
        __half2 h0 = __floats2half2_rn(v.x, v.y);
        __half2 h1 = __floats2half2_rn(v.z, v.w);
        *(uint2*)(owh + j * 4) = make_uint2(*(uint32_t*)&h0, *(uint32_t*)&h1);
    } else if (idx < PREP_TOT) {
        int j = idx - PREP_NA - PREP_NB;
        int k = j / (NQKV / 4), nb = (j % (NQKV / 4)) * 4;
        // segment boundaries (896, 1024) are 4-aligned: vector never straddles
        const float* src = (nb < 896)  ? qw + (size_t)k * 896 + nb
                         : (nb < 1024) ? kw + (size_t)k * 128 + (nb - 896)
                                       : vw + (size_t)k * 128 + (nb - 1024);
        float4 v = *(const float4*)src;
        __half2 h0 = __floats2half2_rn(v.x, v.y);
        __half2 h1 = __floats2half2_rn(v.z, v.w);
        *(uint2*)(wqkv + (size_t)k * NQKV + nb) =
            make_uint2(*(uint32_t*)&h0, *(uint32_t*)&h1);
        if (j < NQKV) {
            bias[j] = (j < 896) ? qb[j]
                    : (j < 1024) ? kb[j - 896] : vb[j - 1024];
        }
    }
}

// ============================================================
// fp16 mma GEMM (unchanged from R8/R9)
// ============================================================
__global__ __launch_bounds__(256, 2) void gemm_h(
    const __half* __restrict__ A, const __half* __restrict__ B,
    const float* __restrict__ bias, float* __restrict__ C,
    int Nw, int Nc, int K)
{
    extern __shared__ __align__(128) char dynsm[];
    __half* As = (__half*)dynsm;                  // [2][128*72]
    __half* Bs = As + 2 * 128 * 72;               // [2][64*136]
    const uint32_t As_u = (uint32_t)__cvta_generic_to_shared(As);
    const uint32_t Bs_u = (uint32_t)__cvta_generic_to_shared(Bs);
    const int STGA = 128 * 72;
    const int STGB = 64 * 136;

    const int tid = threadIdx.x;
    const int lane = tid & 31;
    const int warp = tid >> 5;
    const int warpM = warp >> 2, warpN = warp & 3;
    const int bx = blockIdx.x, by = blockIdx.y;
    const int qrow = lane >> 2, qk = lane & 3;

    const __half* Ag = A + (size_t)(by * 128) * K;
    const __half* Bg = B + bx * 128;
    const int a_row = tid >> 3, a_ch = tid & 7;
    const int b_row = tid >> 4, b_ch = tid & 15;

    float acc[4][4][4];
#pragma unroll
    for (int mf = 0; mf < 4; mf++)
#pragma unroll
        for (int nf = 0; nf < 4; nf++)
#pragma unroll
            for (int i = 0; i < 4; i++) acc[mf][nf][i] = 0.f;

    const int a_row_l = warpM * 64 + (lane & 7) + ((lane >> 3) & 1) * 8;
    const int a_ksel  = (lane >> 4) & 1;
    const int b_col_l = warpN * 32;
    const int b_lane_r = lane & 15;

#pragma unroll
    for (int t = 0; t < 4; t++) {
        int ra = a_row + t * 32;
        cp_async16(As + ra * 72 + a_ch * 8, Ag + (size_t)ra * K + a_ch * 8);
        int rb = b_row + t * 16;
        cp_async16(Bs + rb * 136 + b_ch * 8, Bg + (size_t)rb * Nw + b_ch * 8);
    }
    cp_commit();

    const int NKT = K / 64;
    for (int kt = 0; kt < NKT; kt++) {
        cp_wait0();
        __syncthreads();
        const int cur = kt & 1;
        if (kt + 1 < NKT) {
            const int ko = (kt + 1) * 64;
            __half* Ad = As + (cur ^ 1) * STGA;
            __half* Bd = Bs + (cur ^ 1) * STGB;
#pragma unroll
            for (int t = 0; t < 4; t++) {
                int ra = a_row + t * 32;
                cp_async16(Ad + ra * 72 + a_ch * 8, Ag + (size_t)ra * K + ko + a_ch * 8);
                int rb = b_row + t * 16;
                cp_async16(Bd + rb * 136 + b_ch * 8, Bg + (size_t)(ko + rb) * Nw + b_ch * 8);
            }
        }
        cp_commit();

        const uint32_t Ab = As_u + cur * STGA * 2;
        const uint32_t Bb = Bs_u + cur * STGB * 2;
#pragma unroll
        for (int ch = 0; ch < 4; ch++) {
            uint32_t af[4][4];
#pragma unroll
            for (int mf = 0; mf < 4; mf++) {
                uint32_t sa = Ab + (a_row_l + mf * 16) * 144 + ch * 32 + a_ksel * 16;
                ldsm_x4(af[mf][0], af[mf][1], af[mf][2], af[mf][3], sa);
            }
#pragma unroll
            for (int nf = 0; nf < 4; nf++) {
                uint32_t b0, b1;
                uint32_t sb = Bb + (ch * 16 + b_lane_r) * 272 + (b_col_l + nf * 8) * 2;
                ldsm_x2_trans(b0, b1, sb);
#pragma unroll
                for (int mf = 0; mf < 4; mf++)
                    mma_f16(acc[mf][nf], af[mf][0], af[mf][1], af[mf][2], af[mf][3], b0, b1);
            }
        }
    }

#pragma unroll
    for (int nf = 0; nf < 4; nf++) {
        int col = bx * 128 + warpN * 32 + nf * 8 + qk * 2;
        float b0 = bias ? bias[col] : 0.f;
        float b1 = bias ? bias[col + 1] : 0.f;
#pragma unroll
        for (int mf = 0; mf < 4; mf++) {
            int row = by * 128 + warpM * 64 + mf * 16 + qrow;
            float2 o0 = { acc[mf][nf][0] + b0, acc[mf][nf][1] + b1 };
            float2 o1 = { acc[mf][nf][2] + b0, acc[mf][nf][3] + b1 };
            *(float2*)(C + (size_t)row * Nc + col) = o0;
            *(float2*)(C + (size_t)(row + 8) * Nc + col) = o1;
        }
    }
}

// ============================================================
// RoPE (unchanged)
// ============================================================
__global__ void rope_qkv(float* __restrict__ qkv, __half* __restrict__ kvh,
                         const int* __restrict__ pos)
{
    int idx = blockIdx.x * blockDim.x + threadIdx.x;
    const int tot = MTOT * 18 * 32;
    if (idx >= tot) return;
    int i = idx & 31;
    int slot = (idx >> 5) % 18;
    int t = idx / (32 * 18);

    if (slot >= 16) {
        int h = slot - 16;
        size_t src = (size_t)t * NQKV + 1024 + h * DD + i;
        size_t dst = (size_t)t * 256 + 128 + h * DD + i;
        kvh[dst]      = __float2half(qkv[src]);
        kvh[dst + 32] = __float2half(qkv[src + 32]);
        return;
    }
    float p = (float)pos[t];
    const float cexp = -0.622861517791378f;
    float inv = exp2f((float)i * cexp);
    float ang = p * inv;
    float sn, cs;
    sincosf(ang, &sn, &cs);
    if (slot < HQ) {
        size_t base = (size_t)t * NQKV + slot * DD + i;
        float x1 = qkv[base], x2 = qkv[base + 32];
        qkv[base]      = x1 * cs - x2 * sn;
        qkv[base + 32] = x2 * cs + x1 * sn;
    } else {
        int h = slot - HQ;
        size_t src = (size_t)t * NQKV + 896 + h * DD + i;
        float x1 = qkv[src], x2 = qkv[src + 32];
        size_t dst = (size_t)t * 256 + h * DD + i;
        kvh[dst]      = __float2half(x1 * cs - x2 * sn);
        kvh[dst + 32] = __float2half(x2 * cs + x1 * sn);
    }
}

// ============================================================
// Causal GQA flash attention, fp16 mma.sync. (R9 structure)
// ============================================================
__global__ __launch_bounds__(128, 4) void attn_mma(
    const float* __restrict__ QKV, const __half* __restrict__ KVH,
    __half* __restrict__ O)
{
    extern __shared__ __align__(128) char dynsm2[];
    __half* ks = (__half*)dynsm2;             // [2][64*72]
    __half* vs = ks + 2 * 64 * 72;            // [2][64*72]
    const uint32_t ks_u = (uint32_t)__cvta_generic_to_shared(ks);
    const uint32_t vs_u = (uint32_t)__cvta_generic_to_shared(vs);
    const int STG = 64 * 72;
    const uint32_t ONES = 0x3C003C00u;        // half2(1,1)

    const int bh = blockIdx.x;
    const int b = bh / HQ, h = bh % HQ;
    const int q0 = ((int)gridDim.y - 1 - (int)blockIdx.y) * 64;  // heavy first
    const int kh = h / (HQ / HKV);
    const int tid = threadIdx.x, warp = tid >> 5, lane = tid & 31;
    const int qrow = lane >> 2, qk = lane & 3;
    const float QSCALE = 0.125f * 1.44269504f;  // scale * log2(e)

    const __half* Kb = KVH + (size_t)(b * NN) * 256 + kh * DD;
    const __half* Vb = KVH + (size_t)(b * NN) * 256 + 128 + kh * DD;

    const int ld_row = tid >> 3, ld_ch = tid & 7;

#pragma unroll
    for (int t = 0; t < 4; t++) {
        int r = ld_row + t * 16;
        cp_async16(ks + r * 72 + ld_ch * 8, Kb + (size_t)r * 256 + ld_ch * 8);
        cp_async16(vs + r * 72 + ld_ch * 8, Vb + (size_t)r * 256 + ld_ch * 8);
    }
    cp_commit();

    uint32_t qa[4][4];
    {
        const int r0 = q0 + warp * 16 + qrow;
        const float* qp0 = QKV + (size_t)(b * NN + r0) * NQKV + h * DD;
        const float* qp1 = qp0 + (size_t)8 * NQKV;
#pragma unroll
        for (int ch = 0; ch < 4; ch++) {
            float2 v0 = *(const float2*)(qp0 + ch * 16 + 2 * qk);
            float2 v1 = *(const float2*)(qp1 + ch * 16 + 2 * qk);
            float2 v2 = *(const float2*)(qp0 + ch * 16 + 8 + 2 * qk);
            float2 v3 = *(const float2*)(qp1 + ch * 16 + 8 + 2 * qk);
            qa[ch][0] = h2pack(v0.x * QSCALE, v0.y * QSCALE);
            qa[ch][1] = h2pack(v1.x * QSCALE, v1.y * QSCALE);
            qa[ch][2] = h2pack(v2.x * QSCALE, v2.y * QSCALE);
            qa[ch][3] = h2pack(v3.x * QSCALE, v3.y * QSCALE);
        }
    }

    float o[8][4];
#pragma unroll
    for (int nf = 0; nf < 8; nf++)
#pragma unroll
        for (int i = 0; i < 4; i++) o[nf][i] = 0.f;
    float m0 = -1e30f, m1 = -1e30f, l0 = 0.f, l1 = 0.f;

    const int r0g = q0 + warp * 16 + qrow;
    const int r1g = r0g + 8;
    const int ktiles = q0 / 64 + 1;
    const int kt_diag = ktiles - 1;

    const int k_row_l = lane & 7;
    const int k_ksel  = (lane >> 3) & 1;
    const int k_chsel = (lane >> 4) & 1;
    const int v_row_l = lane & 15;
    const int v_csel  = (lane >> 4) & 1;

    for (int kt = 0; kt < ktiles; kt++) {
        cp_wait0();
        __syncthreads();
        const int cur = kt & 1;
        if (kt + 1 < ktiles) {
            const int base = (kt + 1) * 64;
            __half* kd = ks + (cur ^ 1) * STG;
            __half* vd = vs + (cur ^ 1) * STG;
#pragma unroll
            for (int t = 0; t < 4; t++) {
                int r = ld_row + t * 16;
                cp_async16(kd + r * 72 + ld_ch * 8, Kb + (size_t)(base + r) * 256 + ld_ch * 8);
                cp_async16(vd + r * 72 + ld_ch * 8, Vb + (size_t)(base + r) * 256 + ld_ch * 8);
            }
        }
        cp_commit();

        const uint32_t kc_u = ks_u + cur * STG * 2;

        float sc[8][4];
#pragma unroll
        for (int nf = 0; nf < 8; nf++)
#pragma unroll
            for (int i = 0; i < 4; i++) sc[nf][i] = 0.f;
#pragma unroll
        for (int chp = 0; chp < 2; chp++) {
#pragma unroll
            for (int nf = 0; nf < 8; nf++) {
                uint32_t r0, r1, r2, r3;
                uint32_t sa = kc_u + (nf * 8 + k_row_l) * 144
                            + (chp * 2 + k_chsel) * 32 + k_ksel * 16;
                ldsm_x4(r0, r1, r2, r3, sa);
                mma_f16(sc[nf], qa[chp*2][0], qa[chp*2][1], qa[chp*2][2], qa[chp*2][3], r0, r1);
                mma_f16(sc[nf], qa[chp*2+1][0], qa[chp*2+1][1], qa[chp*2+1][2], qa[chp*2+1][3], r2, r3);
            }
        }

        if (kt == kt_diag) {
#pragma unroll
            for (int nf = 0; nf < 8; nf++) {
                int c = kt * 64 + nf * 8 + qk * 2;
                if (c > r0g)     sc[nf][0] = -1e30f;
                if (c + 1 > r0g) sc[nf][1] = -1e30f;
                if (c > r1g)     sc[nf][2] = -1e30f;
                if (c + 1 > r1g) sc[nf][3] = -1e30f;
            }
        }

        float mx0 = -1e30f, mx1 = -1e30f;
#pragma unroll
        for (int nf = 0; nf < 8; nf++) {
            mx0 = fmaxf(mx0, fmaxf(sc[nf][0], sc[nf][1]));
            mx1 = fmaxf(mx1, fmaxf(sc[nf][2], sc[nf][3]));
        }
        mx0 = fmaxf(mx0, __shfl_xor_sync(0xffffffffu, mx0, 1));
        mx0 = fmaxf(mx0, __shfl_xor_sync(0xffffffffu, mx0, 2));
        mx1 = fmaxf(mx1, __shfl_xor_sync(0xffffffffu, mx1, 1));
        mx1 = fmaxf(mx1, __shfl_xor_sync(0xffffffffu, mx1, 2));
        float mn0 = fmaxf(m0, mx0), mn1 = fmaxf(m1, mx1);
        float al0 = ex2f(m0 - mn0), al1 = ex2f(m1 - mn1);

        uint32_t pa[8][2];
#pragma unroll
        for (int nf = 0; nf < 8; nf++) {
            pa[nf][0] = ex2_h2(h2pack(sc[nf][0] - mn0, sc[nf][1] - mn0));
            pa[nf][1] = ex2_h2(h2pack(sc[nf][2] - mn1, sc[nf][3] - mn1));
        }

        float lt[4] = {0.f, 0.f, 0.f, 0.f};
#pragma unroll
        for (int jk = 0; jk < 4; jk++)
            mma_f16(lt, pa[2*jk][0], pa[2*jk][1], pa[2*jk+1][0], pa[2*jk+1][1],
                    ONES, ONES);
        l0 = l0 * al0 + lt[0];  m0 = mn0;
        l1 = l1 * al1 + lt[2];  m1 = mn1;
#pragma unroll
        for (int nf = 0; nf < 8; nf++) {
            o[nf][0] *= al0; o[nf][1] *= al0;
            o[nf][2] *= al1; o[nf][3] *= al1;
        }

        const uint32_t vc_u = vs_u + cur * STG * 2;
#pragma unroll
        for (int jk = 0; jk < 4; jk++) {
            uint32_t a0 = pa[2*jk][0],   a1 = pa[2*jk][1];
            uint32_t a2 = pa[2*jk+1][0], a3 = pa[2*jk+1][1];
#pragma unroll
            for (int jnp = 0; jnp < 4; jnp++) {
                uint32_t b0, b1, b2, b3;
                uint32_t sb = vc_u + (jk * 16 + v_row_l) * 144
                            + (jnp * 16 + v_csel * 8) * 2;
                ldsm_x4_trans(b0, b1, b2, b3, sb);
                mma_f16(o[2*jnp],   a0, a1, a2, a3, b0, b1);
                mma_f16(o[2*jnp+1], a0, a1, a2, a3, b2, b3);
            }
        }
    }

    float inv0 = 1.0f / (l0 + 1e-8f);
    float inv1 = 1.0f / (l1 + 1e-8f);
    __half* op0 = O + (size_t)(b * NN + r0g) * HID + h * DD;
    __half* op1 = O + (size_t)(b * NN + r1g) * HID + h * DD;
#pragma unroll
    for (int nf = 0; nf < 8; nf++) {
        int d = nf * 8 + qk * 2;
        *(uint32_t*)(op0 + d) = h2pack(o[nf][0] * inv0, o[nf][1] * inv0);
        *(uint32_t*)(op1 + d) = h2pack(o[nf][2] * inv1, o[nf][3] * inv1);
    }
}

// ============================================================
extern "C" void kernel_launch(void* const* d_in, const int* in_sizes, int n_in,
                              void* d_out, int out_size)
{
    const float* hs  = (const float*)d_in[0];
    const int*   pos = (const int*)d_in[1];
    const float* q_w = (const float*)d_in[2];
    const float* q_b = (const float*)d_in[3];
    const float* k_w = (const float*)d_in[4];
    const float* k_b = (const float*)d_in[5];
    const float* v_w = (const float*)d_in[6];
    const float* v_b = (const float*)d_in[7];
    const float* o_w = (const float*)d_in[8];
    float* out = (float*)d_out;

    float *pqkv, *pbqkv;
    __half *pkvh, *poh, *phsh, *pwqkvh, *powh;
    cudaGetSymbolAddress((void**)&pqkv,   g_qkv);
    cudaGetSymbolAddress((void**)&pkvh,   g_kvh);
    cudaGetSymbolAddress((void**)&poh,    g_oh);
    cudaGetSymbolAddress((void**)&phsh,   g_hsh);
    cudaGetSymbolAddress((void**)&pwqkvh, g_wqkvh);
    cudaGetSymbolAddress((void**)&pbqkv,  g_bqkv);
    cudaGetSymbolAddress((void**)&powh,   g_owh);

    const int GEMM_SMEM = 2 * (128*72 + 64*136) * 2;   // 71680 B
    const int ATTN_SMEM = 2 * (64*72 + 64*72) * 2;     // 36864 B
    cudaFuncSetAttribute(gemm_h,   cudaFuncAttributeMaxDynamicSharedMemorySize, GEMM_SMEM);
    cudaFuncSetAttribute(attn_mma, cudaFuncAttributeMaxDynamicSharedMemorySize, ATTN_SMEM);

    // fused prep (single launch)
    prep_all<<<(PREP_TOT + 255) / 256, 256>>>(
        (const float4*)hs, (const float4*)o_w,
        q_w, k_w, v_w, q_b, k_b, v_b,
        phsh, powh, pwqkvh, pbqkv);
    // fused QKV projection
    gemm_h<<<dim3(9, 32), 256, GEMM_SMEM>>>(phsh, pwqkvh, pbqkv, pqkv, NQKV, NQKV, HID);
    // RoPE
    {
        int tot = MTOT * 18 * 32;
        rope_qkv<<<(tot + 255) / 256, 256>>>(pqkv, pkvh, pos);
    }
    // causal GQA attention -> fp16 O
    attn_mma<<<dim3(BB * HQ, NN / 64), 128, ATTN_SMEM>>>(pqkv, pkvh, poh);
    // output projection
    gemm_h<<<dim3(7, 32), 256, GEMM_SMEM>>>(poh, powh, nullptr, out, HID, HID, HID);
}

// round 11
// speedup vs baseline: 1.6525x; 1.0622x over previous
#include <cuda_runtime.h>
#include <cuda_fp16.h>
#include <math.h>
#include <stdint.h>

#define BB   2
#define NN   2048
#define HID  896
#define HQ   14
#define HKV  2
#define DD   64
#define MTOT (BB*NN)          // 4096 tokens
#define NQKV 1152             // 896 Q + 128 K + 128 V

// ---- scratch (device globals: no allocations allowed) ----
__device__ __half g_qkvh[MTOT*NQKV];   // fused QKV proj output, fp16
__device__ __half g_oh[MTOT*HID];      // attention out, fp16
__device__ __half g_hsh[MTOT*HID];     // fp16 hidden_states
__device__ __half g_wqkvh[HID*NQKV];   // packed [896(k)][1152(n)] fp16
__device__ float  g_bqkv[NQKV];        // packed bias fp32
__device__ __half g_owh[HID*HID];      // o_w [896(k)][896(n)] fp16

// ============================================================
// helpers
// ============================================================
__device__ __forceinline__ float ex2f(float x) {
    float y;
    asm("ex2.approx.ftz.f32 %0, %1;" : "=f"(y) : "f"(x));
    return y;
}
__device__ __forceinline__ uint32_t ex2_h2(uint32_t x) {
    uint32_t y;
    asm("ex2.approx.f16x2 %0, %1;" : "=r"(y) : "r"(x));
    return y;
}
__device__ __forceinline__ void mma_f16(float c[4],
    uint32_t a0, uint32_t a1, uint32_t a2, uint32_t a3,
    uint32_t b0, uint32_t b1)
{
    asm volatile(
        "mma.sync.aligned.m16n8k16.row.col.f32.f16.f16.f32 "
        "{%0,%1,%2,%3}, {%4,%5,%6,%7}, {%8,%9}, {%0,%1,%2,%3};\n"
        : "+f"(c[0]), "+f"(c[1]), "+f"(c[2]), "+f"(c[3])
        : "r"(a0), "r"(a1), "r"(a2), "r"(a3), "r"(b0), "r"(b1));
}
__device__ __forceinline__ void ldsm_x4(uint32_t& r0, uint32_t& r1,
                                        uint32_t& r2, uint32_t& r3, uint32_t sa)
{
    asm volatile("ldmatrix.sync.aligned.m8n8.x4.shared.b16 {%0,%1,%2,%3}, [%4];"
                 : "=r"(r0), "=r"(r1), "=r"(r2), "=r"(r3) : "r"(sa));
}
__device__ __forceinline__ void ldsm_x4_trans(uint32_t& r0, uint32_t& r1,
                                              uint32_t& r2, uint32_t& r3, uint32_t sa)
{
    asm volatile("ldmatrix.sync.aligned.m8n8.x4.trans.shared.b16 {%0,%1,%2,%3}, [%4];"
                 : "=r"(r0), "=r"(r1), "=r"(r2), "=r"(r3) : "r"(sa));
}
__device__ __forceinline__ void ldsm_x2_trans(uint32_t& r0, uint32_t& r1, uint32_t sa)
{
    asm volatile("ldmatrix.sync.aligned.m8n8.x2.trans.shared.b16 {%0,%1}, [%2];"
                 : "=r"(r0), "=r"(r1) : "r"(sa));
}
__device__ __forceinline__ void cp_async16(void* sdst, const void* gsrc) {
    unsigned sa = (unsigned)__cvta_generic_to_shared(sdst);
    asm volatile("cp.async.cg.shared.global [%0], [%1], 16;\n"
                 :: "r"(sa), "l"(gsrc));
}
__device__ __forceinline__ void cp_commit() {
    asm volatile("cp.async.commit_group;\n");
}
__device__ __forceinline__ void cp_wait0() {
    asm volatile("cp.async.wait_group 0;\n");
}
__device__ __forceinline__ uint32_t h2pack(float x, float y) {
    __half2 h = __floats2half2_rn(x, y);
    return *(uint32_t*)&h;
}
__device__ __forceinline__ float2 h2unpack(uint32_t u) {
    __half2 h = *(__half2*)&u;
    return __half22float2(h);
}

// ============================================================
// fused prep: hs->fp16, o_w->fp16, qkv pack (one launch, coalesced)
// ============================================================
#define PREP_NA (MTOT*HID/4)      // 917504
#define PREP_NB (HID*HID/4)       // 200704
#define PREP_NC (HID*NQKV/4)      // 258048
#define PREP_TOT (PREP_NA + PREP_NB + PREP_NC)

__global__ void prep_all(
    const float4* __restrict__ hs, const float4* __restrict__ ow,
    const float* __restrict__ qw, const float* __restrict__ kw,
    const float* __restrict__ vw, const float* __restrict__ qb,
    const float* __restrict__ kb, const float* __restrict__ vb,
    __half* __restrict__ hsh, __half* __restrict__ owh,
    __half* __restrict__ wqkv, float* __restrict__ bias)
{
    int idx = blockIdx.x * blockDim.x + threadIdx.x;
    if (idx < PREP_NA) {
        float4 v = hs[idx];
        __half2 h0 = __floats2half2_rn(v.x, v.y);
        __half2 h1 = __floats2half2_rn(v.z, v.w);
        *(uint2*)(hsh + idx * 4) = make_uint2(*(uint32_t*)&h0, *(uint32_t*)&h1);
    } else if (idx < PREP_NA + PREP_NB) {
        int j = idx - PREP_NA;
        float4 v = ow[j];
        __half2 h0 = __floats2half2_rn(v.x, v.y);
        __half2 h1 = __floats2half2_rn(v.z, v.w);
        *(uint2*)(owh + j * 4) = make_uint2(*(uint32_t*)&h0, *(uint32_t*)&h1);
    } else if (idx < PREP_TOT) {
        int j = idx - PREP_NA - PREP_NB;
        int k = j / (NQKV / 4), nb = (j % (NQKV / 4)) * 4;
        const float* src = (nb < 896)  ? qw + (size_t)k * 896 + nb
                         : (nb < 1024) ? kw + (size_t)k * 128 + (nb - 896)
                                       : vw + (size_t)k * 128 + (nb - 1024);
        float4 v = *(const float4*)src;
        __half2 h0 = __floats2half2_rn(v.x, v.y);
        __half2 h1 = __floats2half2_rn(v.z, v.w);
        *(uint2*)(wqkv + (size_t)k * NQKV + nb) =
            make_uint2(*(uint32_t*)&h0, *(uint32_t*)&h1);
        if (j < NQKV) {
            bias[j] = (j < 896) ? qb[j]
                    : (j < 1024) ? kb[j - 896] : vb[j - 1024];
        }
    }
}

// ============================================================
// fp16 mma GEMM, templated output type (half or float).
// ============================================================
template <typename OutT>
__global__ __launch_bounds__(256, 2) void gemm_h(
    const __half* __restrict__ A, const __half* __restrict__ B,
    const float* __restrict__ bias, OutT* __restrict__ C,
    int Nw, int Nc, int K)
{
    extern __shared__ __align__(128) char dynsm[];
    __half* As = (__half*)dynsm;                  // [2][128*72]
    __half* Bs = As + 2 * 128 * 72;               // [2][64*136]
    const uint32_t As_u = (uint32_t)__cvta_generic_to_shared(As);
    const uint32_t Bs_u = (uint32_t)__cvta_generic_to_shared(Bs);
    const int STGA = 128 * 72;
    const int STGB = 64 * 136;

    const int tid = threadIdx.x;
    const int lane = tid & 31;
    const int warp = tid >> 5;
    const int warpM = warp >> 2, warpN = warp & 3;
    const int bx = blockIdx.x, by = blockIdx.y;
    const int qrow = lane >> 2, qk = lane & 3;

    const __half* Ag = A + (size_t)(by * 128) * K;
    const __half* Bg = B + bx * 128;
    const int a_row = tid >> 3, a_ch = tid & 7;
    const int b_row = tid >> 4, b_ch = tid & 15;

    float acc[4][4][4];
#pragma unroll
    for (int mf = 0; mf < 4; mf++)
#pragma unroll
        for (int nf = 0; nf < 4; nf++)
#pragma unroll
            for (int i = 0; i < 4; i++) acc[mf][nf][i] = 0.f;

    const int a_row_l = warpM * 64 + (lane & 7) + ((lane >> 3) & 1) * 8;
    const int a_ksel  = (lane >> 4) & 1;
    const int b_col_l = warpN * 32;
    const int b_lane_r = lane & 15;

#pragma unroll
    for (int t = 0; t < 4; t++) {
        int ra = a_row + t * 32;
        cp_async16(As + ra * 72 + a_ch * 8, Ag + (size_t)ra * K + a_ch * 8);
        int rb = b_row + t * 16;
        cp_async16(Bs + rb * 136 + b_ch * 8, Bg + (size_t)rb * Nw + b_ch * 8);
    }
    cp_commit();

    const int NKT = K / 64;
    for (int kt = 0; kt < NKT; kt++) {
        cp_wait0();
        __syncthreads();
        const int cur = kt & 1;
        if (kt + 1 < NKT) {
            const int ko = (kt + 1) * 64;
            __half* Ad = As + (cur ^ 1) * STGA;
            __half* Bd = Bs + (cur ^ 1) * STGB;
#pragma unroll
            for (int t = 0; t < 4; t++) {
                int ra = a_row + t * 32;
                cp_async16(Ad + ra * 72 + a_ch * 8, Ag + (size_t)ra * K + ko + a_ch * 8);
                int rb = b_row + t * 16;
                cp_async16(Bd + rb * 136 + b_ch * 8, Bg + (size_t)(ko + rb) * Nw + b_ch * 8);
            }
        }
        cp_commit();

        const uint32_t Ab = As_u + cur * STGA * 2;
        const uint32_t Bb = Bs_u + cur * STGB * 2;
#pragma unroll
        for (int ch = 0; ch < 4; ch++) {
            uint32_t af[4][4];
#pragma unroll
            for (int mf = 0; mf < 4; mf++) {
                uint32_t sa = Ab + (a_row_l + mf * 16) * 144 + ch * 32 + a_ksel * 16;
                ldsm_x4(af[mf][0], af[mf][1], af[mf][2], af[mf][3], sa);
            }
#pragma unroll
            for (int nf = 0; nf < 4; nf++) {
                uint32_t b0, b1;
                uint32_t sb = Bb + (ch * 16 + b_lane_r) * 272 + (b_col_l + nf * 8) * 2;
                ldsm_x2_trans(b0, b1, sb);
#pragma unroll
                for (int mf = 0; mf < 4; mf++)
                    mma_f16(acc[mf][nf], af[mf][0], af[mf][1], af[mf][2], af[mf][3], b0, b1);
            }
        }
    }

#pragma unroll
    for (int nf = 0; nf < 4; nf++) {
        int col = bx * 128 + warpN * 32 + nf * 8 + qk * 2;
        float b0 = bias ? bias[col] : 0.f;
        float b1 = bias ? bias[col + 1] : 0.f;
#pragma unroll
        for (int mf = 0; mf < 4; mf++) {
            int row = by * 128 + warpM * 64 + mf * 16 + qrow;
            float v00 = acc[mf][nf][0] + b0, v01 = acc[mf][nf][1] + b1;
            float v10 = acc[mf][nf][2] + b0, v11 = acc[mf][nf][3] + b1;
            if constexpr (sizeof(OutT) == 2) {
                *(uint32_t*)(C + (size_t)row * Nc + col)       = h2pack(v00, v01);
                *(uint32_t*)(C + (size_t)(row + 8) * Nc + col) = h2pack(v10, v11);
            } else {
                *(float2*)(C + (size_t)row * Nc + col)       = make_float2(v00, v01);
                *(float2*)(C + (size_t)(row + 8) * Nc + col) = make_float2(v10, v11);
            }
        }
    }
}

// ============================================================
// K-only RoPE, in place, fp16 (2 heads)
// ============================================================
__global__ void rope_k(__half* __restrict__ qkvh, const int* __restrict__ pos)
{
    int idx = blockIdx.x * blockDim.x + threadIdx.x;
    if (idx >= MTOT * HKV * 32) return;
    int i = idx & 31;
    int h = (idx >> 5) & 1;
    int t = idx >> 6;
    float p = (float)pos[t];
    const float cexp = -0.622861517791378f;  // -log2(1e6)/32
    float ang = p * exp2f((float)i * cexp);
    float sn, cs;
    sincosf(ang, &sn, &cs);
    size_t base = (size_t)t * NQKV + 896 + h * DD + i;
    float x1 = __half2float(qkvh[base]);
    float x2 = __half2float(qkvh[base + 32]);
    qkvh[base]      = __float2half(x1 * cs - x2 * sn);
    qkvh[base + 32] = __float2half(x2 * cs + x1 * sn);
}

// ============================================================
// Causal GQA flash attention, fp16 mma.sync, Q-RoPE inline.
// K/V read directly from qkvh (stride NQKV).
// ============================================================
__global__ __launch_bounds__(128, 4) void attn_mma(
    const __half* __restrict__ QKV, const int* __restrict__ pos,
    __half* __restrict__ O)
{
    extern __shared__ __align__(128) char dynsm2[];
    __half* ks = (__half*)dynsm2;             // [2][64*72]
    __half* vs = ks + 2 * 64 * 72;            // [2][64*72]
    const uint32_t ks_u = (uint32_t)__cvta_generic_to_shared(ks);
    const uint32_t vs_u = (uint32_t)__cvta_generic_to_shared(vs);
    const int STG = 64 * 72;
    const uint32_t ONES = 0x3C003C00u;        // half2(1,1)

    const int bh = blockIdx.x;
    const int b = bh / HQ, h = bh % HQ;
    const int q0 = ((int)gridDim.y - 1 - (int)blockIdx.y) * 64;  // heavy first
    const int kh = h / (HQ / HKV);
    const int tid = threadIdx.x, warp = tid >> 5, lane = tid & 31;
    const int qrow = lane >> 2, qk = lane & 3;
    const float QSCALE = 0.125f * 1.44269504f;  // scale * log2(e)

    const __half* Kb = QKV + (size_t)(b * NN) * NQKV + 896 + kh * DD;
    const __half* Vb = QKV + (size_t)(b * NN) * NQKV + 1024 + kh * DD;

    const int ld_row = tid >> 3, ld_ch = tid & 7;

    // prologue: K/V tile 0 -> stage 0
#pragma unroll
    for (int t = 0; t < 4; t++) {
        int r = ld_row + t * 16;
        cp_async16(ks + r * 72 + ld_ch * 8, Kb + (size_t)r * NQKV + ld_ch * 8);
        cp_async16(vs + r * 72 + ld_ch * 8, Vb + (size_t)r * NQKV + ld_ch * 8);
    }
    cp_commit();

    const int r0g = q0 + warp * 16 + qrow;
    const int r1g = r0g + 8;

    // --- Q fragments, RoPE applied inline (fp16 source) ---
    uint32_t qa[4][4];
    {
        const __half* qp0 = QKV + (size_t)(b * NN + r0g) * NQKV + h * DD;
        const __half* qp1 = qp0 + (size_t)8 * NQKV;
        float2 f[4][4];
#pragma unroll
        for (int ch = 0; ch < 4; ch++) {
            f[ch][0] = h2unpack(*(const uint32_t*)(qp0 + ch * 16 + 2 * qk));
            f[ch][1] = h2unpack(*(const uint32_t*)(qp1 + ch * 16 + 2 * qk));
            f[ch][2] = h2unpack(*(const uint32_t*)(qp0 + ch * 16 + 8 + 2 * qk));
            f[ch][3] = h2unpack(*(const uint32_t*)(qp1 + ch * 16 + 8 + 2 * qk));
        }
        const float p0 = (float)pos[b * NN + r0g];
        const float p1 = (float)pos[b * NN + r1g];
        const float cexp = -0.622861517791378f;
#pragma unroll
        for (int chlo = 0; chlo < 2; chlo++) {
#pragma unroll
            for (int j = 0; j < 4; j++) {
                float p = (j & 1) ? p1 : p0;
                int i0 = chlo * 16 + ((j >> 1) ? 8 : 0) + 2 * qk;
                float sn0, cs0, sn1, cs1;
                sincosf(p * exp2f((float)i0 * cexp), &sn0, &cs0);
                sincosf(p * exp2f((float)(i0 + 1) * cexp), &sn1, &cs1);
                cs0 *= QSCALE; sn0 *= QSCALE; cs1 *= QSCALE; sn1 *= QSCALE;
                float2 lo = f[chlo][j], hi = f[chlo + 2][j];
                qa[chlo][j]     = h2pack(lo.x * cs0 - hi.x * sn0,
                                         lo.y * cs1 - hi.y * sn1);
                qa[chlo + 2][j] = h2pack(hi.x * cs0 + lo.x * sn0,
                                         hi.y * cs1 + lo.y * sn1);
            }
        }
    }

    float o[8][4];
#pragma unroll
    for (int nf = 0; nf < 8; nf++)
#pragma unroll
        for (int i = 0; i < 4; i++) o[nf][i] = 0.f;
    float m0 = -1e30f, m1 = -1e30f, l0 = 0.f, l1 = 0.f;

    const int ktiles = q0 / 64 + 1;
    const int kt_diag = ktiles - 1;

    const int k_row_l = lane & 7;
    const int k_ksel  = (lane >> 3) & 1;
    const int k_chsel = (lane >> 4) & 1;
    const int v_row_l = lane & 15;
    const int v_csel  = (lane >> 4) & 1;

    for (int kt = 0; kt < ktiles; kt++) {
        cp_wait0();
        __syncthreads();
        const int cur = kt & 1;
        if (kt + 1 < ktiles) {
            const int base = (kt + 1) * 64;
            __half* kd = ks + (cur ^ 1) * STG;
            __half* vd = vs + (cur ^ 1) * STG;
#pragma unroll
            for (int t = 0; t < 4; t++) {
                int r = ld_row + t * 16;
                cp_async16(kd + r * 72 + ld_ch * 8, Kb + (size_t)(base + r) * NQKV + ld_ch * 8);
                cp_async16(vd + r * 72 + ld_ch * 8, Vb + (size_t)(base + r) * NQKV + ld_ch * 8);
            }
        }
        cp_commit();

        const uint32_t kc_u = ks_u + cur * STG * 2;

        // ---- S = Q @ K^T (log2-scaled) ----
        float sc[8][4];
#pragma unroll
        for (int nf = 0; nf < 8; nf++)
#pragma unroll
            for (int i = 0; i < 4; i++) sc[nf][i] = 0.f;
#pragma unroll
        for (int chp = 0; chp < 2; chp++) {
#pragma unroll
            for (int nf = 0; nf < 8; nf++) {
                uint32_t r0, r1, r2, r3;
                uint32_t sa = kc_u + (nf * 8 + k_row_l) * 144
                            + (chp * 2 + k_chsel) * 32 + k_ksel * 16;
                ldsm_x4(r0, r1, r2, r3, sa);
                mma_f16(sc[nf], qa[chp*2][0], qa[chp*2][1], qa[chp*2][2], qa[chp*2][3], r0, r1);
                mma_f16(sc[nf], qa[chp*2+1][0], qa[chp*2+1][1], qa[chp*2+1][2], qa[chp*2+1][3], r2, r3);
            }
        }

        // ---- causal mask ----
        if (kt == kt_diag) {
#pragma unroll
            for (int nf = 0; nf < 8; nf++) {
                int c = kt * 64 + nf * 8 + qk * 2;
                if (c > r0g)     sc[nf][0] = -1e30f;
                if (c + 1 > r0g) sc[nf][1] = -1e30f;
                if (c > r1g)     sc[nf][2] = -1e30f;
                if (c + 1 > r1g) sc[nf][3] = -1e30f;
            }
        }

        // ---- online softmax (log2 domain, f16x2 ex2) ----
        float mx0 = -1e30f, mx1 = -1e30f;
#pragma unroll
        for (int nf = 0; nf < 8; nf++) {
            mx0 = fmaxf(mx0, fmaxf(sc[nf][0], sc[nf][1]));
            mx1 = fmaxf(mx1, fmaxf(sc[nf][2], sc[nf][3]));
        }
        mx0 = fmaxf(mx0, __shfl_xor_sync(0xffffffffu, mx0, 1));
        mx0 = fmaxf(mx0, __shfl_xor_sync(0xffffffffu, mx0, 2));
        mx1 = fmaxf(mx1, __shfl_xor_sync(0xffffffffu, mx1, 1));
        mx1 = fmaxf(mx1, __shfl_xor_sync(0xffffffffu, mx1, 2));
        float mn0 = fmaxf(m0, mx0), mn1 = fmaxf(m1, mx1);
        float al0 = ex2f(m0 - mn0), al1 = ex2f(m1 - mn1);

        uint32_t pa[8][2];
#pragma unroll
        for (int nf = 0; nf < 8; nf++) {
            pa[nf][0] = ex2_h2(h2pack(sc[nf][0] - mn0, sc[nf][1] - mn0));
            pa[nf][1] = ex2_h2(h2pack(sc[nf][2] - mn1, sc[nf][3] - mn1));
        }

        float lt[4] = {0.f, 0.f, 0.f, 0.f};
#pragma unroll
        for (int jk = 0; jk < 4; jk++)
            mma_f16(lt, pa[2*jk][0], pa[2*jk][1], pa[2*jk+1][0], pa[2*jk+1][1],
                    ONES, ONES);
        l0 = l0 * al0 + lt[0];  m0 = mn0;
        l1 = l1 * al1 + lt[2];  m1 = mn1;
#pragma unroll
        for (int nf = 0; nf < 8; nf++) {
            o[nf][0] *= al0; o[nf][1] *= al0;
            o[nf][2] *= al1; o[nf][3] *= al1;
        }

        const uint32_t vc_u = vs_u + cur * STG * 2;
#pragma unroll
        for (int jk = 0; jk < 4; jk++) {
            uint32_t a0 = pa[2*jk][0],   a1 = pa[2*jk][1];
            uint32_t a2 = pa[2*jk+1][0], a3 = pa[2*jk+1][1];
#pragma unroll
            for (int jnp = 0; jnp < 4; jnp++) {
                uint32_t b0, b1, b2, b3;
                uint32_t sb = vc_u + (jk * 16 + v_row_l) * 144
                            + (jnp * 16 + v_csel * 8) * 2;
                ldsm_x4_trans(b0, b1, b2, b3, sb);
                mma_f16(o[2*jnp],   a0, a1, a2, a3, b0, b1);
                mma_f16(o[2*jnp+1], a0, a1, a2, a3, b2, b3);
            }
        }
    }

    float inv0 = 1.0f / (l0 + 1e-8f);
    float inv1 = 1.0f / (l1 + 1e-8f);
    __half* op0 = O + (size_t)(b * NN + r0g) * HID + h * DD;
    __half* op1 = O + (size_t)(b * NN + r1g) * HID + h * DD;
#pragma unroll
    for (int nf = 0; nf < 8; nf++) {
        int d = nf * 8 + qk * 2;
        *(uint32_t*)(op0 + d) = h2pack(o[nf][0] * inv0, o[nf][1] * inv0);
        *(uint32_t*)(op1 + d) = h2pack(o[nf][2] * inv1, o[nf][3] * inv1);
    }
}

// ============================================================
extern "C" void kernel_launch(void* const* d_in, const int* in_sizes, int n_in,
                              void* d_out, int out_size)
{
    const float* hs  = (const float*)d_in[0];
    const int*   pos = (const int*)d_in[1];
    const float* q_w = (const float*)d_in[2];
    const float* q_b = (const float*)d_in[3];
    const float* k_w = (const float*)d_in[4];
    const float* k_b = (const float*)d_in[5];
    const float* v_w = (const float*)d_in[6];
    const float* v_b = (const float*)d_in[7];
    const float* o_w = (const float*)d_in[8];
    float* out = (float*)d_out;

    float* pbqkv;
    __half *pqkvh, *poh, *phsh, *pwqkvh, *powh;
    cudaGetSymbolAddress((void**)&pqkvh,  g_qkvh);
    cudaGetSymbolAddress((void**)&poh,    g_oh);
    cudaGetSymbolAddress((void**)&phsh,   g_hsh);
    cudaGetSymbolAddress((void**)&pwqkvh, g_wqkvh);
    cudaGetSymbolAddress((void**)&pbqkv,  g_bqkv);
    cudaGetSymbolAddress((void**)&powh,   g_owh);

    const int GEMM_SMEM = 2 * (128*72 + 64*136) * 2;   // 71680 B
    const int ATTN_SMEM = 2 * (64*72 + 64*72) * 2;     // 36864 B
    cudaFuncSetAttribute(gemm_h<__half>, cudaFuncAttributeMaxDynamicSharedMemorySize, GEMM_SMEM);
    cudaFuncSetAttribute(gemm_h<float>,  cudaFuncAttributeMaxDynamicSharedMemorySize, GEMM_SMEM);
    cudaFuncSetAttribute(attn_mma,       cudaFuncAttributeMaxDynamicSharedMemorySize, ATTN_SMEM);

    // fused prep (single launch)
    prep_all<<<(PREP_TOT + 255) / 256, 256>>>(
        (const float4*)hs, (const float4*)o_w,
        q_w, k_w, v_w, q_b, k_b, v_b,
        phsh, powh, pwqkvh, pbqkv);
    // fused QKV projection -> fp16
    gemm_h<__half><<<dim3(9, 32), 256, GEMM_SMEM>>>(phsh, pwqkvh, pbqkv, pqkvh,
                                                    NQKV, NQKV, HID);
    // RoPE on K only (in place, fp16)
    {
        int tot = MTOT * HKV * 32;
        rope_k<<<(tot + 255) / 256, 256>>>(pqkvh, pos);
    }
    // causal GQA attention (Q-RoPE inline) -> fp16 O
    attn_mma<<<dim3(BB * HQ, NN / 64), 128, ATTN_SMEM>>>(pqkvh, pos, poh);
    // output projection -> fp32 out
    gemm_h<float><<<dim3(7, 32), 256, GEMM_SMEM>>>(poh, powh, nullptr, out,
                                                   HID, HID, HID);
}

// round 12
// speedup vs baseline: 1.6888x; 1.0220x over previous
#include <cuda_runtime.h>
#include <cuda_fp16.h>
#include <math.h>
#include <stdint.h>

#define BB   2
#define NN   2048
#define HID  896
#define HQ   14
#define HKV  2
#define DD   64
#define MTOT (BB*NN)          // 4096 tokens
#define NQKV 1152             // 896 Q + 128 K + 128 V

// ---- scratch (device globals: no allocations allowed) ----
__device__ __half g_qkvh[MTOT*NQKV];   // fused QKV proj output, fp16
__device__ __half g_oh[MTOT*HID];      // attention out, fp16
__device__ __half g_hsh[MTOT*HID];     // fp16 hidden_states
__device__ __half g_wqkvh[HID*NQKV];   // packed [896(k)][1152(n)] fp16
__device__ float  g_bqkv[NQKV];        // packed bias fp32
__device__ __half g_owh[HID*HID];      // o_w [896(k)][896(n)] fp16

// ============================================================
// helpers
// ============================================================
__device__ __forceinline__ float ex2f(float x) {
    float y;
    asm("ex2.approx.ftz.f32 %0, %1;" : "=f"(y) : "f"(x));
    return y;
}
__device__ __forceinline__ uint32_t ex2_h2(uint32_t x) {
    uint32_t y;
    asm("ex2.approx.f16x2 %0, %1;" : "=r"(y) : "r"(x));
    return y;
}
__device__ __forceinline__ void mma_f16(float c[4],
    uint32_t a0, uint32_t a1, uint32_t a2, uint32_t a3,
    uint32_t b0, uint32_t b1)
{
    asm volatile(
        "mma.sync.aligned.m16n8k16.row.col.f32.f16.f16.f32 "
        "{%0,%1,%2,%3}, {%4,%5,%6,%7}, {%8,%9}, {%0,%1,%2,%3};\n"
        : "+f"(c[0]), "+f"(c[1]), "+f"(c[2]), "+f"(c[3])
        : "r"(a0), "r"(a1), "r"(a2), "r"(a3), "r"(b0), "r"(b1));
}
__device__ __forceinline__ void ldsm_x4(uint32_t& r0, uint32_t& r1,
                                        uint32_t& r2, uint32_t& r3, uint32_t sa)
{
    asm volatile("ldmatrix.sync.aligned.m8n8.x4.shared.b16 {%0,%1,%2,%3}, [%4];"
                 : "=r"(r0), "=r"(r1), "=r"(r2), "=r"(r3) : "r"(sa));
}
__device__ __forceinline__ void ldsm_x4_trans(uint32_t& r0, uint32_t& r1,
                                              uint32_t& r2, uint32_t& r3, uint32_t sa)
{
    asm volatile("ldmatrix.sync.aligned.m8n8.x4.trans.shared.b16 {%0,%1,%2,%3}, [%4];"
                 : "=r"(r0), "=r"(r1), "=r"(r2), "=r"(r3) : "r"(sa));
}
__device__ __forceinline__ void cp_async16(void* sdst, const void* gsrc) {
    unsigned sa = (unsigned)__cvta_generic_to_shared(sdst);
    asm volatile("cp.async.cg.shared.global [%0], [%1], 16;\n"
                 :: "r"(sa), "l"(gsrc));
}
__device__ __forceinline__ void cp_commit() {
    asm volatile("cp.async.commit_group;\n");
}
__device__ __forceinline__ void cp_wait0() {
    asm volatile("cp.async.wait_group 0;\n");
}
__device__ __forceinline__ uint32_t h2pack(float x, float y) {
    __half2 h = __floats2half2_rn(x, y);
    return *(uint32_t*)&h;
}
__device__ __forceinline__ float2 h2unpack(uint32_t u) {
    __half2 h = *(__half2*)&u;
    return __half22float2(h);
}

// ============================================================
// fused prep: hs->fp16, o_w->fp16, qkv pack (one launch, coalesced)
// ============================================================
#define PREP_NA (MTOT*HID/4)      // 917504
#define PREP_NB (HID*HID/4)       // 200704
#define PREP_NC (HID*NQKV/4)      // 258048
#define PREP_TOT (PREP_NA + PREP_NB + PREP_NC)

__global__ void prep_all(
    const float4* __restrict__ hs, const float4* __restrict__ ow,
    const float* __restrict__ qw, const float* __restrict__ kw,
    const float* __restrict__ vw, const float* __restrict__ qb,
    const float* __restrict__ kb, const float* __restrict__ vb,
    __half* __restrict__ hsh, __half* __restrict__ owh,
    __half* __restrict__ wqkv, float* __restrict__ bias)
{
    int idx = blockIdx.x * blockDim.x + threadIdx.x;
    if (idx < PREP_NA) {
        float4 v = hs[idx];
        __half2 h0 = __floats2half2_rn(v.x, v.y);
        __half2 h1 = __floats2half2_rn(v.z, v.w);
        *(uint2*)(hsh + idx * 4) = make_uint2(*(uint32_t*)&h0, *(uint32_t*)&h1);
    } else if (idx < PREP_NA + PREP_NB) {
        int j = idx - PREP_NA;
        float4 v = ow[j];
        __half2 h0 = __floats2half2_rn(v.x, v.y);
        __half2 h1 = __floats2half2_rn(v.z, v.w);
        *(uint2*)(owh + j * 4) = make_uint2(*(uint32_t*)&h0, *(uint32_t*)&h1);
    } else if (idx < PREP_TOT) {
        int j = idx - PREP_NA - PREP_NB;
        int k = j / (NQKV / 4), nb = (j % (NQKV / 4)) * 4;
        const float* src = (nb < 896)  ? qw + (size_t)k * 896 + nb
                         : (nb < 1024) ? kw + (size_t)k * 128 + (nb - 896)
                                       : vw + (size_t)k * 128 + (nb - 1024);
        float4 v = *(const float4*)src;
        __half2 h0 = __floats2half2_rn(v.x, v.y);
        __half2 h1 = __floats2half2_rn(v.z, v.w);
        *(uint2*)(wqkv + (size_t)k * NQKV + nb) =
            make_uint2(*(uint32_t*)&h0, *(uint32_t*)&h1);
        if (j < NQKV) {
            bias[j] = (j < 896) ? qb[j]
                    : (j < 1024) ? kb[j - 896] : vb[j - 1024];
        }
    }
}

// ============================================================
// fp16 mma GEMM, templated output type. B frags via ldsm.x4.trans.
// ============================================================
template <typename OutT>
__global__ __launch_bounds__(256, 2) void gemm_h(
    const __half* __restrict__ A, const __half* __restrict__ B,
    const float* __restrict__ bias, OutT* __restrict__ C,
    int Nw, int Nc, int K)
{
    extern __shared__ __align__(128) char dynsm[];
    __half* As = (__half*)dynsm;                  // [2][128*72]
    __half* Bs = As + 2 * 128 * 72;               // [2][64*136]
    const uint32_t As_u = (uint32_t)__cvta_generic_to_shared(As);
    const uint32_t Bs_u = (uint32_t)__cvta_generic_to_shared(Bs);
    const int STGA = 128 * 72;
    const int STGB = 64 * 136;

    const int tid = threadIdx.x;
    const int lane = tid & 31;
    const int warp = tid >> 5;
    const int warpM = warp >> 2, warpN = warp & 3;
    const int bx = blockIdx.x, by = blockIdx.y;
    const int qrow = lane >> 2, qk = lane & 3;

    const __half* Ag = A + (size_t)(by * 128) * K;
    const __half* Bg = B + bx * 128;
    const int a_row = tid >> 3, a_ch = tid & 7;
    const int b_row = tid >> 4, b_ch = tid & 15;

    float acc[4][4][4];
#pragma unroll
    for (int mf = 0; mf < 4; mf++)
#pragma unroll
        for (int nf = 0; nf < 4; nf++)
#pragma unroll
            for (int i = 0; i < 4; i++) acc[mf][nf][i] = 0.f;

    const int a_row_l = warpM * 64 + (lane & 7) + ((lane >> 3) & 1) * 8;
    const int a_ksel  = (lane >> 4) & 1;
    // B x4t addressing: rows ch*16 + (lane&15), col half select (lane>>4)*8
    const int b_lane_r = lane & 15;
    const int b_csel   = (lane >> 4) & 1;
    const int b_col_l  = warpN * 32;

#pragma unroll
    for (int t = 0; t < 4; t++) {
        int ra = a_row + t * 32;
        cp_async16(As + ra * 72 + a_ch * 8, Ag + (size_t)ra * K + a_ch * 8);
        int rb = b_row + t * 16;
        cp_async16(Bs + rb * 136 + b_ch * 8, Bg + (size_t)rb * Nw + b_ch * 8);
    }
    cp_commit();

    const int NKT = K / 64;
    for (int kt = 0; kt < NKT; kt++) {
        cp_wait0();
        __syncthreads();
        const int cur = kt & 1;
        if (kt + 1 < NKT) {
            const int ko = (kt + 1) * 64;
            __half* Ad = As + (cur ^ 1) * STGA;
            __half* Bd = Bs + (cur ^ 1) * STGB;
#pragma unroll
            for (int t = 0; t < 4; t++) {
                int ra = a_row + t * 32;
                cp_async16(Ad + ra * 72 + a_ch * 8, Ag + (size_t)ra * K + ko + a_ch * 8);
                int rb = b_row + t * 16;
                cp_async16(Bd + rb * 136 + b_ch * 8, Bg + (size_t)(ko + rb) * Nw + b_ch * 8);
            }
        }
        cp_commit();

        const uint32_t Ab = As_u + cur * STGA * 2;
        const uint32_t Bb = Bs_u + cur * STGB * 2;
#pragma unroll
        for (int ch = 0; ch < 4; ch++) {
            uint32_t af[4][4];
#pragma unroll
            for (int mf = 0; mf < 4; mf++) {
                uint32_t sa = Ab + (a_row_l + mf * 16) * 144 + ch * 32 + a_ksel * 16;
                ldsm_x4(af[mf][0], af[mf][1], af[mf][2], af[mf][3], sa);
            }
#pragma unroll
            for (int jp = 0; jp < 2; jp++) {
                uint32_t b0, b1, b2, b3;
                uint32_t sb = Bb + (ch * 16 + b_lane_r) * 272
                            + (b_col_l + jp * 16 + b_csel * 8) * 2;
                ldsm_x4_trans(b0, b1, b2, b3, sb);
#pragma unroll
                for (int mf = 0; mf < 4; mf++) {
                    mma_f16(acc[mf][2*jp],   af[mf][0], af[mf][1], af[mf][2], af[mf][3], b0, b1);
                    mma_f16(acc[mf][2*jp+1], af[mf][0], af[mf][1], af[mf][2], af[mf][3], b2, b3);
                }
            }
        }
    }

#pragma unroll
    for (int nf = 0; nf < 4; nf++) {
        int col = bx * 128 + warpN * 32 + nf * 8 + qk * 2;
        float b0 = bias ? bias[col] : 0.f;
        float b1 = bias ? bias[col + 1] : 0.f;
#pragma unroll
        for (int mf = 0; mf < 4; mf++) {
            int row = by * 128 + warpM * 64 + mf * 16 + qrow;
            float v00 = acc[mf][nf][0] + b0, v01 = acc[mf][nf][1] + b1;
            float v10 = acc[mf][nf][2] + b0, v11 = acc[mf][nf][3] + b1;
            if constexpr (sizeof(OutT) == 2) {
                *(uint32_t*)(C + (size_t)row * Nc + col)       = h2pack(v00, v01);
                *(uint32_t*)(C + (size_t)(row + 8) * Nc + col) = h2pack(v10, v11);
            } else {
                *(float2*)(C + (size_t)row * Nc + col)       = make_float2(v00, v01);
                *(float2*)(C + (size_t)(row + 8) * Nc + col) = make_float2(v10, v11);
            }
        }
    }
}

// ============================================================
// K-only RoPE, in place, fp16 (2 heads)
// ============================================================
__global__ void rope_k(__half* __restrict__ qkvh, const int* __restrict__ pos)
{
    int idx = blockIdx.x * blockDim.x + threadIdx.x;
    if (idx >= MTOT * HKV * 32) return;
    int i = idx & 31;
    int h = (idx >> 5) & 1;
    int t = idx >> 6;
    float p = (float)pos[t];
    const float cexp = -0.622861517791378f;  // -log2(1e6)/32
    float ang = p * exp2f((float)i * cexp);
    float sn, cs;
    sincosf(ang, &sn, &cs);
    size_t base = (size_t)t * NQKV + 896 + h * DD + i;
    float x1 = __half2float(qkvh[base]);
    float x2 = __half2float(qkvh[base + 32]);
    qkvh[base]      = __float2half(x1 * cs - x2 * sn);
    qkvh[base + 32] = __float2half(x2 * cs + x1 * sn);
}

// ============================================================
// Causal GQA flash attention, fp16 mma.sync, Q-RoPE inline.
// (unchanged from R11)
// ============================================================
__global__ __launch_bounds__(128, 4) void attn_mma(
    const __half* __restrict__ QKV, const int* __restrict__ pos,
    __half* __restrict__ O)
{
    extern __shared__ __align__(128) char dynsm2[];
    __half* ks = (__half*)dynsm2;             // [2][64*72]
    __half* vs = ks + 2 * 64 * 72;            // [2][64*72]
    const uint32_t ks_u = (uint32_t)__cvta_generic_to_shared(ks);
    const uint32_t vs_u = (uint32_t)__cvta_generic_to_shared(vs);
    const int STG = 64 * 72;
    const uint32_t ONES = 0x3C003C00u;        // half2(1,1)

    const int bh = blockIdx.x;
    const int b = bh / HQ, h = bh % HQ;
    const int q0 = ((int)gridDim.y - 1 - (int)blockIdx.y) * 64;  // heavy first
    const int kh = h / (HQ / HKV);
    const int tid = threadIdx.x, warp = tid >> 5, lane = tid & 31;
    const int qrow = lane >> 2, qk = lane & 3;
    const float QSCALE = 0.125f * 1.44269504f;  // scale * log2(e)

    const __half* Kb = QKV + (size_t)(b * NN) * NQKV + 896 + kh * DD;
    const __half* Vb = QKV + (size_t)(b * NN) * NQKV + 1024 + kh * DD;

    const int ld_row = tid >> 3, ld_ch = tid & 7;

#pragma unroll
    for (int t = 0; t < 4; t++) {
        int r = ld_row + t * 16;
        cp_async16(ks + r * 72 + ld_ch * 8, Kb + (size_t)r * NQKV + ld_ch * 8);
        cp_async16(vs + r * 72 + ld_ch * 8, Vb + (size_t)r * NQKV + ld_ch * 8);
    }
    cp_commit();

    const int r0g = q0 + warp * 16 + qrow;
    const int r1g = r0g + 8;

    // --- Q fragments, RoPE applied inline (fp16 source) ---
    uint32_t qa[4][4];
    {
        const __half* qp0 = QKV + (size_t)(b * NN + r0g) * NQKV + h * DD;
        const __half* qp1 = qp0 + (size_t)8 * NQKV;
        float2 f[4][4];
#pragma unroll
        for (int ch = 0; ch < 4; ch++) {
            f[ch][0] = h2unpack(*(const uint32_t*)(qp0 + ch * 16 + 2 * qk));
            f[ch][1] = h2unpack(*(const uint32_t*)(qp1 + ch * 16 + 2 * qk));
            f[ch][2] = h2unpack(*(const uint32_t*)(qp0 + ch * 16 + 8 + 2 * qk));
            f[ch][3] = h2unpack(*(const uint32_t*)(qp1 + ch * 16 + 8 + 2 * qk));
        }
        const float p0 = (float)pos[b * NN + r0g];
        const float p1 = (float)pos[b * NN + r1g];
        const float cexp = -0.622861517791378f;
#pragma unroll
        for (int chlo = 0; chlo < 2; chlo++) {
#pragma unroll
            for (int j = 0; j < 4; j++) {
                float p = (j & 1) ? p1 : p0;
                int i0 = chlo * 16 + ((j >> 1) ? 8 : 0) + 2 * qk;
                float sn0, cs0, sn1, cs1;
                sincosf(p * exp2f((float)i0 * cexp), &sn0, &cs0);
                sincosf(p * exp2f((float)(i0 + 1) * cexp), &sn1, &cs1);
                cs0 *= QSCALE; sn0 *= QSCALE; cs1 *= QSCALE; sn1 *= QSCALE;
                float2 lo = f[chlo][j], hi = f[chlo + 2][j];
                qa[chlo][j]     = h2pack(lo.x * cs0 - hi.x * sn0,
                                         lo.y * cs1 - hi.y * sn1);
                qa[chlo + 2][j] = h2pack(hi.x * cs0 + lo.x * sn0,
                                         hi.y * cs1 + lo.y * sn1);
            }
        }
    }

    float o[8][4];
#pragma unroll
    for (int nf = 0; nf < 8; nf++)
#pragma unroll
        for (int i = 0; i < 4; i++) o[nf][i] = 0.f;
    float m0 = -1e30f, m1 = -1e30f, l0 = 0.f, l1 = 0.f;

    const int ktiles = q0 / 64 + 1;
    const int kt_diag = ktiles - 1;

    const int k_row_l = lane & 7;
    const int k_ksel  = (lane >> 3) & 1;
    const int k_chsel = (lane >> 4) & 1;
    const int v_row_l = lane & 15;
    const int v_csel  = (lane >> 4) & 1;

    for (int kt = 0; kt < ktiles; kt++) {
        cp_wait0();
        __syncthreads();
        const int cur = kt & 1;
        if (kt + 1 < ktiles) {
            const int base = (kt + 1) * 64;
            __half* kd = ks + (cur ^ 1) * STG;
            __half* vd = vs + (cur ^ 1) * STG;
#pragma unroll
            for (int t = 0; t < 4; t++) {
                int r = ld_row + t * 16;
                cp_async16(kd + r * 72 + ld_ch * 8, Kb + (size_t)(base + r) * NQKV + ld_ch * 8);
                cp_async16(vd + r * 72 + ld_ch * 8, Vb + (size_t)(base + r) * NQKV + ld_ch * 8);
            }
        }
        cp_commit();

        const uint32_t kc_u = ks_u + cur * STG * 2;

        // ---- S = Q @ K^T (log2-scaled) ----
        float sc[8][4];
#pragma unroll
        for (int nf = 0; nf < 8; nf++)
#pragma unroll
            for (int i = 0; i < 4; i++) sc[nf][i] = 0.f;
#pragma unroll
        for (int chp = 0; chp < 2; chp++) {
#pragma unroll
            for (int nf = 0; nf < 8; nf++) {
                uint32_t r0, r1, r2, r3;
                uint32_t sa = kc_u + (nf * 8 + k_row_l) * 144
                            + (chp * 2 + k_chsel) * 32 + k_ksel * 16;
                ldsm_x4(r0, r1, r2, r3, sa);
                mma_f16(sc[nf], qa[chp*2][0], qa[chp*2][1], qa[chp*2][2], qa[chp*2][3], r0, r1);
                mma_f16(sc[nf], qa[chp*2+1][0], qa[chp*2+1][1], qa[chp*2+1][2], qa[chp*2+1][3], r2, r3);
            }
        }

        // ---- causal mask ----
        if (kt == kt_diag) {
#pragma unroll
            for (int nf = 0; nf < 8; nf++) {
                int c = kt * 64 + nf * 8 + qk * 2;
                if (c > r0g)     sc[nf][0] = -1e30f;
                if (c + 1 > r0g) sc[nf][1] = -1e30f;
                if (c > r1g)     sc[nf][2] = -1e30f;
                if (c + 1 > r1g) sc[nf][3] = -1e30f;
            }
        }

        // ---- online softmax (log2 domain, f16x2 ex2) ----
        float mx0 = -1e30f, mx1 = -1e30f;
#pragma unroll
        for (int nf = 0; nf < 8; nf++) {
            mx0 = fmaxf(mx0, fmaxf(sc[nf][0], sc[nf][1]));
            mx1 = fmaxf(mx1, fmaxf(sc[nf][2], sc[nf][3]));
        }
        mx0 = fmaxf(mx0, __shfl_xor_sync(0xffffffffu, mx0, 1));
        mx0 = fmaxf(mx0, __shfl_xor_sync(0xffffffffu, mx0, 2));
        mx1 = fmaxf(mx1, __shfl_xor_sync(0xffffffffu, mx1, 1));
        mx1 = fmaxf(mx1, __shfl_xor_sync(0xffffffffu, mx1, 2));
        float mn0 = fmaxf(m0, mx0), mn1 = fmaxf(m1, mx1);
        float al0 = ex2f(m0 - mn0), al1 = ex2f(m1 - mn1);

        uint32_t pa[8][2];
#pragma unroll
        for (int nf = 0; nf < 8; nf++) {
            pa[nf][0] = ex2_h2(h2pack(sc[nf][0] - mn0, sc[nf][1] - mn0));
            pa[nf][1] = ex2_h2(h2pack(sc[nf][2] - mn1, sc[nf][3] - mn1));
        }

        float lt[4] = {0.f, 0.f, 0.f, 0.f};
#pragma unroll
        for (int jk = 0; jk < 4; jk++)
            mma_f16(lt, pa[2*jk][0], pa[2*jk][1], pa[2*jk+1][0], pa[2*jk+1][1],
                    ONES, ONES);
        l0 = l0 * al0 + lt[0];  m0 = mn0;
        l1 = l1 * al1 + lt[2];  m1 = mn1;
#pragma unroll
        for (int nf = 0; nf < 8; nf++) {
            o[nf][0] *= al0; o[nf][1] *= al0;
            o[nf][2] *= al1; o[nf][3] *= al1;
        }

        const uint32_t vc_u = vs_u + cur * STG * 2;
#pragma unroll
        for (int jk = 0; jk < 4; jk++) {
            uint32_t a0 = pa[2*jk][0],   a1 = pa[2*jk][1];
            uint32_t a2 = pa[2*jk+1][0], a3 = pa[2*jk+1][1];
#pragma unroll
            for (int jnp = 0; jnp < 4; jnp++) {
                uint32_t b0, b1, b2, b3;
                uint32_t sb = vc_u + (jk * 16 + v_row_l) * 144
                            + (jnp * 16 + v_csel * 8) * 2;
                ldsm_x4_trans(b0, b1, b2, b3, sb);
                mma_f16(o[2*jnp],   a0, a1, a2, a3, b0, b1);
                mma_f16(o[2*jnp+1], a0, a1, a2, a3, b2, b3);
            }
        }
    }

    float inv0 = 1.0f / (l0 + 1e-8f);
    float inv1 = 1.0f / (l1 + 1e-8f);
    __half* op0 = O + (size_t)(b * NN + r0g) * HID + h * DD;
    __half* op1 = O + (size_t)(b * NN + r1g) * HID + h * DD;
#pragma unroll
    for (int nf = 0; nf < 8; nf++) {
        int d = nf * 8 + qk * 2;
        *(uint32_t*)(op0 + d) = h2pack(o[nf][0] * inv0, o[nf][1] * inv0);
        *(uint32_t*)(op1 + d) = h2pack(o[nf][2] * inv1, o[nf][3] * inv1);
    }
}

// ============================================================
extern "C" void kernel_launch(void* const* d_in, const int* in_sizes, int n_in,
                              void* d_out, int out_size)
{
    const float* hs  = (const float*)d_in[0];
    const int*   pos = (const int*)d_in[1];
    const float* q_w = (const float*)d_in[2];
    const float* q_b = (const float*)d_in[3];
    const float* k_w = (const float*)d_in[4];
    const float* k_b = (const float*)d_in[5];
    const float* v_w = (const float*)d_in[6];
    const float* v_b = (const float*)d_in[7];
    const float* o_w = (const float*)d_in[8];
    float* out = (float*)d_out;

    float* pbqkv;
    __half *pqkvh, *poh, *phsh, *pwqkvh, *powh;
    cudaGetSymbolAddress((void**)&pqkvh,  g_qkvh);
    cudaGetSymbolAddress((void**)&poh,    g_oh);
    cudaGetSymbolAddress((void**)&phsh,   g_hsh);
    cudaGetSymbolAddress((void**)&pwqkvh, g_wqkvh);
    cudaGetSymbolAddress((void**)&pbqkv,  g_bqkv);
    cudaGetSymbolAddress((void**)&powh,   g_owh);

    const int GEMM_SMEM = 2 * (128*72 + 64*136) * 2;   // 71680 B
    const int ATTN_SMEM = 2 * (64*72 + 64*72) * 2;     // 36864 B
    cudaFuncSetAttribute(gemm_h<__half>, cudaFuncAttributeMaxDynamicSharedMemorySize, GEMM_SMEM);
    cudaFuncSetAttribute(gemm_h<float>,  cudaFuncAttributeMaxDynamicSharedMemorySize, GEMM_SMEM);
    cudaFuncSetAttribute(attn_mma,       cudaFuncAttributeMaxDynamicSharedMemorySize, ATTN_SMEM);

    // fused prep (single launch)
    prep_all<<<(PREP_TOT + 255) / 256, 256>>>(
        (const float4*)hs, (const float4*)o_w,
        q_w, k_w, v_w, q_b, k_b, v_b,
        phsh, powh, pwqkvh, pbqkv);
    // fused QKV projection -> fp16
    gemm_h<__half><<<dim3(9, 32), 256, GEMM_SMEM>>>(phsh, pwqkvh, pbqkv, pqkvh,
                                                    NQKV, NQKV, HID);
    // RoPE on K only (in place, fp16)
    {
        int tot = MTOT * HKV * 32;
        rope_k<<<(tot + 255) / 256, 256>>>(pqkvh, pos);
    }
    // causal GQA attention (Q-RoPE inline) -> fp16 O
    attn_mma<<<dim3(BB * HQ, NN / 64), 128, ATTN_SMEM>>>(pqkvh, pos, poh);
    // output projection -> fp32 out
    gemm_h<float><<<dim3(7, 32), 256, GEMM_SMEM>>>(poh, powh, nullptr, out,
                                                   HID, HID, HID);
}